// round 3
// baseline (speedup 1.0000x reference)
#include <cuda_runtime.h>
#include <cuda_bf16.h>
#include <math.h>

#define BSZ   512
#define NN    400
#define GRID  20
#define EDIM  128
#define H1    256
#define NF    15
#define EPSF  1e-5f

// ---------------- scratch (static device allocations) ----------------
__device__ float g_feat[(size_t)NN * BSZ * NF];          // [n][b][15]
__device__ float g_h0  [(size_t)NN * BSZ * H1];          // [n][b][256]  relu(feat@W0+b0)
__device__ float g_x1  [(size_t)NN * BSZ * EDIM];        // [n][b][128]  relu(BN1(h0)@W1+b1)
__device__ int   g_seed[BSZ];
__device__ float g_a1[NN], g_d1[NN], g_a2[NN], g_d2[NN];
__device__ float g_s2[NN], g_ss2[NN];
__device__ float g_S1[EDIM];                              // colsum of W1

// ---------------- K1: features + nearest indices ----------------
__global__ __launch_bounds__(128) void k1_feat(const float* __restrict__ agvs,
                                               const float* __restrict__ nodes) {
    int b = blockIdx.x;
    int tid = threadIdx.x;
    __shared__ float featb[NN * NF];      // 24KB
    __shared__ float sn[NN * 2];
    for (int i = tid; i < NN * NF; i += 128) featb[i] = 0.f;
    for (int i = tid; i < NN * 2;  i += 128) sn[i] = nodes[i];
    __syncthreads();

    const float* arow = agvs + (size_t)b * 160;   // 10 x 16
    if (tid < 70) {
        int a = tid / 7, k = tid % 7;
        float cx = arow[a * 16 + 2 + 2 * k];
        float cy = arow[a * 16 + 3 + 2 * k];
        float best = 3.402823466e38f;
        int bi = 0;
        for (int n = 0; n < NN; n++) {
            float dx = cx - sn[2 * n];
            float dy = cy - sn[2 * n + 1];
            float d = dx * dx + dy * dy;
            if (d < best) { best = d; bi = n; }
        }
        if (a == 0) {
            atomicAdd(&featb[bi * NF + k], 1.0f);
            if (k == 1) g_seed[b] = bi;           // cols 4:6 = main point #1
        } else {
            atomicAdd(&featb[bi * NF + 7 + k], 1.0f);
        }
    }
    // distance feature: || nodes - obs_main[6:8] ||
    float c6 = arow[6], c7 = arow[7];
    for (int n = tid; n < NN; n += 128) {
        float dx = sn[2 * n] - c6, dy = sn[2 * n + 1] - c7;
        featb[n * NF + 14] = sqrtf(dx * dx + dy * dy);
    }
    __syncthreads();
    for (int i = tid; i < NN * NF; i += 128) {
        int n = i / NF, k = i % NF;
        g_feat[((size_t)n * BSZ + b) * NF + k] = featb[i];
    }
}

// ---------------- block reduce helper (256 threads) ----------------
__device__ __forceinline__ float blockReduce256(float v, float* red) {
    int tid = threadIdx.x;
    red[tid] = v; __syncthreads();
    #pragma unroll
    for (int o = 128; o > 0; o >>= 1) {
        if (tid < o) red[tid] += red[tid + o];
        __syncthreads();
    }
    float r = red[0];
    __syncthreads();
    return r;
}

// ---------------- K2a: GEMM1 + BN1 stats (block per node) ----------------
__global__ __launch_bounds__(256) void k2_gemm1(const float* __restrict__ W0,
                                                const float* __restrict__ b0,
                                                const float* __restrict__ g1,
                                                const float* __restrict__ be1) {
    int n = blockIdx.x;
    int tid = threadIdx.x;                 // = output channel c (0..255)
    __shared__ float W0s[NF * H1];         // 15KB
    __shared__ float fs[16 * NF];
    __shared__ float red[256];
    for (int i = tid; i < NF * H1; i += 256) W0s[i] = W0[i];
    float bias = b0[tid];
    float s = 0.f, s2 = 0.f;
    const float* fbase = g_feat + (size_t)n * BSZ * NF;
    float* hbase = g_h0 + (size_t)n * BSZ * H1;
    for (int bb0 = 0; bb0 < BSZ; bb0 += 16) {
        __syncthreads();
        for (int i = tid; i < 16 * NF; i += 256) fs[i] = fbase[(size_t)bb0 * NF + i];
        __syncthreads();
        #pragma unroll 4
        for (int q = 0; q < 16; q++) {
            float v = bias;
            #pragma unroll
            for (int k = 0; k < NF; k++) v = fmaf(fs[q * NF + k], W0s[k * H1 + tid], v);
            v = fmaxf(v, 0.f);
            hbase[(size_t)(bb0 + q) * H1 + tid] = v;
            s += v; s2 = fmaf(v, v, s2);
        }
    }
    float tot = blockReduce256(s, red);
    float tot2 = blockReduce256(s2, red);
    if (tid == 0) {
        const float cnt = (float)(BSZ * H1);
        float m = tot / cnt;
        float var = tot2 / cnt - m * m;
        float a = g1[n] * rsqrtf(var + EPSF);
        g_a1[n] = a;
        g_d1[n] = be1[n] - m * a;
    }
}

// ---------------- K2b: colsum(W1), zero BN2 stats ----------------
__global__ void k2b_prep(const float* __restrict__ W1) {
    int t = threadIdx.x;
    if (t < EDIM) {
        float s = 0.f;
        for (int c = 0; c < H1; c++) s += W1[c * EDIM + t];
        g_S1[t] = s;
    }
    if (t < NN) { g_s2[t] = 0.f; g_ss2[t] = 0.f; }
}

// ---------------- K3: main SGEMM  x1 = relu(a1*(h0@W1) + d1*S1 + b1) ----------------
#define BM 128
#define BN 128
#define BK 16
__global__ __launch_bounds__(256) void k3_gemm2(const float* __restrict__ W1,
                                                const float* __restrict__ b1) {
    const int tid = threadIdx.x;
    const int mtile = blockIdx.x;                    // 0..1599
    __shared__ float As[2][BK][BM];                  // 16KB
    __shared__ float Bs[2][BK][BN];                  // 16KB
    __shared__ float red[256];

    const float* Ag = g_h0 + (size_t)mtile * BM * H1;

    const int trow = tid >> 4;   // 0..15
    const int tcol = tid & 15;   // 0..15
    const int trow8 = trow * 8, tcol8 = tcol * 8;

    // A loads: 512 float4 per tile; thread owns q0=tid, q1=tid+256
    const int q0 = tid, q1 = tid + 256;
    const int arow0 = q0 >> 2, ak0 = (q0 & 3) << 2;
    const int arow1 = q1 >> 2, ak1 = (q1 & 3) << 2;
    // B loads: 512 float4 per tile
    const int bk0 = q0 >> 5, bj0 = (q0 & 31) << 2;
    const int bk1 = q1 >> 5, bj1 = (q1 & 31) << 2;

    float acc[8][8];
    #pragma unroll
    for (int i = 0; i < 8; i++)
        #pragma unroll
        for (int j = 0; j < 8; j++) acc[i][j] = 0.f;

    // prime stage 0
    {
        float4 a0 = *reinterpret_cast<const float4*>(Ag + (size_t)arow0 * H1 + ak0);
        float4 a1 = *reinterpret_cast<const float4*>(Ag + (size_t)arow1 * H1 + ak1);
        float4 b0v = *reinterpret_cast<const float4*>(W1 + (size_t)bk0 * EDIM + bj0);
        float4 b1v = *reinterpret_cast<const float4*>(W1 + (size_t)bk1 * EDIM + bj1);
        As[0][ak0 + 0][arow0] = a0.x; As[0][ak0 + 1][arow0] = a0.y;
        As[0][ak0 + 2][arow0] = a0.z; As[0][ak0 + 3][arow0] = a0.w;
        As[0][ak1 + 0][arow1] = a1.x; As[0][ak1 + 1][arow1] = a1.y;
        As[0][ak1 + 2][arow1] = a1.z; As[0][ak1 + 3][arow1] = a1.w;
        *reinterpret_cast<float4*>(&Bs[0][bk0][bj0]) = b0v;
        *reinterpret_cast<float4*>(&Bs[0][bk1][bj1]) = b1v;
    }
    __syncthreads();

    int st = 0;
    #pragma unroll 1
    for (int kt = 0; kt < H1 / BK; kt++) {
        float4 na0, na1, nb0, nb1;
        const bool more = (kt + 1 < H1 / BK);
        if (more) {
            int k0 = (kt + 1) * BK;
            na0 = *reinterpret_cast<const float4*>(Ag + (size_t)arow0 * H1 + k0 + ak0);
            na1 = *reinterpret_cast<const float4*>(Ag + (size_t)arow1 * H1 + k0 + ak1);
            nb0 = *reinterpret_cast<const float4*>(W1 + (size_t)(k0 + bk0) * EDIM + bj0);
            nb1 = *reinterpret_cast<const float4*>(W1 + (size_t)(k0 + bk1) * EDIM + bj1);
        }
        #pragma unroll
        for (int k = 0; k < BK; k++) {
            float4 av0 = *reinterpret_cast<const float4*>(&As[st][k][trow8]);
            float4 av1 = *reinterpret_cast<const float4*>(&As[st][k][trow8 + 4]);
            float4 bv0 = *reinterpret_cast<const float4*>(&Bs[st][k][tcol8]);
            float4 bv1 = *reinterpret_cast<const float4*>(&Bs[st][k][tcol8 + 4]);
            float ar[8] = {av0.x, av0.y, av0.z, av0.w, av1.x, av1.y, av1.z, av1.w};
            float br[8] = {bv0.x, bv0.y, bv0.z, bv0.w, bv1.x, bv1.y, bv1.z, bv1.w};
            #pragma unroll
            for (int i = 0; i < 8; i++)
                #pragma unroll
                for (int j = 0; j < 8; j++) acc[i][j] = fmaf(ar[i], br[j], acc[i][j]);
        }
        if (more) {
            int so = st ^ 1;
            As[so][ak0 + 0][arow0] = na0.x; As[so][ak0 + 1][arow0] = na0.y;
            As[so][ak0 + 2][arow0] = na0.z; As[so][ak0 + 3][arow0] = na0.w;
            As[so][ak1 + 0][arow1] = na1.x; As[so][ak1 + 1][arow1] = na1.y;
            As[so][ak1 + 2][arow1] = na1.z; As[so][ak1 + 3][arow1] = na1.w;
            *reinterpret_cast<float4*>(&Bs[so][bk0][bj0]) = nb0;
            *reinterpret_cast<float4*>(&Bs[so][bk1][bj1]) = nb1;
            __syncthreads();
            st = so;
        }
    }

    // epilogue: BN1 fold + relu, store x1, accumulate BN2 stats
    const int n = mtile >> 2;   // 4 tiles per node (512/128)
    const float a1v = g_a1[n], d1v = g_d1[n];
    float S1r[8], b1r[8];
    #pragma unroll
    for (int j = 0; j < 8; j++) { S1r[j] = g_S1[tcol8 + j]; b1r[j] = b1[tcol8 + j]; }
    float s = 0.f, s2 = 0.f;
    #pragma unroll
    for (int i = 0; i < 8; i++) {
        size_t r = (size_t)mtile * BM + trow8 + i;
        float v[8];
        #pragma unroll
        for (int j = 0; j < 8; j++) {
            float x = fmaxf(fmaf(a1v, acc[i][j], fmaf(d1v, S1r[j], b1r[j])), 0.f);
            v[j] = x;
            s += x; s2 = fmaf(x, x, s2);
        }
        *reinterpret_cast<float4*>(g_x1 + r * EDIM + tcol8)     = make_float4(v[0], v[1], v[2], v[3]);
        *reinterpret_cast<float4*>(g_x1 + r * EDIM + tcol8 + 4) = make_float4(v[4], v[5], v[6], v[7]);
    }
    float tot = blockReduce256(s, red);
    float tot2 = blockReduce256(s2, red);
    if (tid == 0) {
        atomicAdd(&g_s2[n], tot);
        atomicAdd(&g_ss2[n], tot2);
    }
}

// ---------------- K2c: finalize BN2 affine ----------------
__global__ void k2c_fin(const float* __restrict__ g2, const float* __restrict__ be2) {
    int n = blockIdx.x * blockDim.x + threadIdx.x;
    if (n < NN) {
        const float cnt = (float)(BSZ * EDIM);
        float m = g_s2[n] / cnt;
        float var = g_ss2[n] / cnt - m * m;
        float a = g2[n] * rsqrtf(var + EPSF);
        g_a2[n] = a;
        g_d2[n] = be2[n] - m * a;
    }
}

// ---------------- K4: masked 2-hop graph conv + output ----------------
__global__ __launch_bounds__(128) void k4_conv(const float* __restrict__ Wc,
                                               const float* __restrict__ bc,
                                               float* __restrict__ out) {
    int b = blockIdx.x;
    int tid = threadIdx.x;   // channel j
    __shared__ float xs[13][EDIM];
    __shared__ float hs[13][EDIM];
    __shared__ int   nodelist[13];
    __shared__ float dinv_s[13];
    __shared__ int   locmap[25];
    __shared__ int   cnt_s;

    int seed = g_seed[b];
    int si = seed / GRID, sj = seed % GRID;
    if (tid == 0) {
        int cnt = 0;
        for (int di = -2; di <= 2; di++)
            for (int dj = -2; dj <= 2; dj++) {
                int lm = -1;
                if (abs(di) + abs(dj) <= 2) {
                    int i = si + di, j = sj + dj;
                    if (i >= 0 && i < GRID && j >= 0 && j < GRID) {
                        lm = cnt;
                        nodelist[cnt] = i * GRID + j;
                        cnt++;
                    }
                }
                locmap[(di + 2) * 5 + (dj + 2)] = lm;
            }
        cnt_s = cnt;
    }
    __syncthreads();
    const int M = cnt_s;

    if (tid < M) {
        int n = nodelist[tid];
        int i = n / GRID, j = n % GRID;
        int di = i - si + 2, dj = j - sj + 2;
        int nb = 0;
        if (di - 1 >= 0 && locmap[(di - 1) * 5 + dj] >= 0) nb++;
        if (di + 1 < 5  && locmap[(di + 1) * 5 + dj] >= 0) nb++;
        if (dj - 1 >= 0 && locmap[di * 5 + dj - 1] >= 0) nb++;
        if (dj + 1 < 5  && locmap[di * 5 + dj + 1] >= 0) nb++;
        dinv_s[tid] = rsqrtf((float)(1 + nb));
    }
    __syncthreads();

    // load BN2-affined x at masked nodes
    for (int m = 0; m < M; m++) {
        int n = nodelist[m];
        xs[m][tid] = fmaf(g_a2[n], g_x1[((size_t)n * BSZ + b) * EDIM + tid], g_d2[n]);
    }
    __syncthreads();

    for (int it = 0; it < 2; it++) {
        const float* wc = Wc + (size_t)it * EDIM * EDIM;
        for (int m = 0; m < M; m++) {
            float acc = 0.f;
            #pragma unroll 8
            for (int c = 0; c < EDIM; c++)
                acc = fmaf(xs[m][c], __ldg(wc + (size_t)c * EDIM + tid), acc);
            hs[m][tid] = acc;
        }
        __syncthreads();   // all reads of xs done
        float bcv = bc[it * EDIM + tid];
        for (int m = 0; m < M; m++) {
            int n = nodelist[m];
            int i = n / GRID, j = n % GRID;
            int di = i - si + 2, dj = j - sj + 2;
            float dm = dinv_s[m];
            float acc = dm * dm * hs[m][tid];
            int u;
            if (di - 1 >= 0 && (u = locmap[(di - 1) * 5 + dj]) >= 0) acc = fmaf(dinv_s[u] * dm, hs[u][tid], acc);
            if (di + 1 < 5  && (u = locmap[(di + 1) * 5 + dj]) >= 0) acc = fmaf(dinv_s[u] * dm, hs[u][tid], acc);
            if (dj - 1 >= 0 && (u = locmap[di * 5 + dj - 1]) >= 0) acc = fmaf(dinv_s[u] * dm, hs[u][tid], acc);
            if (dj + 1 < 5  && (u = locmap[di * 5 + dj + 1]) >= 0) acc = fmaf(dinv_s[u] * dm, hs[u][tid], acc);
            xs[m][tid] = acc + bcv;
        }
        __syncthreads();
    }

    float s = 0.f;
    for (int m = 0; m < M; m++) s += xs[m][tid];
    out[(size_t)b * EDIM + tid] = s / (float)M;
}

// ---------------- launch ----------------
extern "C" void kernel_launch(void* const* d_in, const int* in_sizes, int n_in,
                              void* d_out, int out_size) {
    const float* agvs  = (const float*)d_in[0];
    const float* nodes = (const float*)d_in[1];
    // d_in[2] = edge_index (int32) — fixed symmetric 4-neighbor grid, handled analytically
    const float* W0  = (const float*)d_in[3];
    const float* b0  = (const float*)d_in[4];
    const float* g1  = (const float*)d_in[5];
    const float* be1 = (const float*)d_in[6];
    const float* W1  = (const float*)d_in[7];
    const float* b1  = (const float*)d_in[8];
    const float* g2  = (const float*)d_in[9];
    const float* be2 = (const float*)d_in[10];
    const float* Wc  = (const float*)d_in[11];
    const float* bc  = (const float*)d_in[12];
    float* out = (float*)d_out;

    k1_feat<<<BSZ, 128>>>(agvs, nodes);
    k2_gemm1<<<NN, 256>>>(W0, b0, g1, be1);
    k2b_prep<<<1, 512>>>(W1);
    k3_gemm2<<<(NN * BSZ) / BM, 256>>>(W1, b1);
    k2c_fin<<<1, 512>>>(g2, be2);
    k4_conv<<<BSZ, 128>>>(Wc, bc, out);
}

// round 4
// speedup vs baseline: 1.4987x; 1.4987x over previous
#include <cuda_runtime.h>
#include <cuda_bf16.h>
#include <math.h>

#define BSZ   512
#define NN    400
#define GRID  20
#define EDIM  128
#define H1    256
#define NF    15
#define EPSF  1e-5f

// ---------------- scratch (static device allocations) ----------------
__device__ float g_feat[(size_t)NN * BSZ * NF];          // [n][b][15]
__device__ float g_xc[(size_t)BSZ * 13 * EDIM];          // compact masked x1 (pre-BN2)
__device__ int   g_seed[BSZ];
__device__ float g_a1[NN], g_d1[NN], g_a2[NN], g_d2[NN];
__device__ float g_s2[NN], g_ss2[NN];
__device__ float g_S1[EDIM];                              // colsum of W1

// ---------------- packed f32x2 helpers ----------------
__device__ __forceinline__ unsigned long long ffma2(unsigned long long a,
                                                    unsigned long long b,
                                                    unsigned long long c) {
    unsigned long long d;
    asm("fma.rn.f32x2 %0, %1, %2, %3;" : "=l"(d) : "l"(a), "l"(b), "l"(c));
    return d;
}
__device__ __forceinline__ unsigned long long pack2f(float x) {
    unsigned long long d;
    unsigned int u = __float_as_uint(x);
    asm("mov.b64 %0, {%1, %1};" : "=l"(d) : "r"(u));
    return d;
}
__device__ __forceinline__ float2 unpack2(unsigned long long p) {
    unsigned int lo, hi;
    asm("mov.b64 {%0, %1}, %2;" : "=r"(lo), "=r"(hi) : "l"(p));
    return make_float2(__uint_as_float(lo), __uint_as_float(hi));
}

// local index of node n inside the 2-hop diamond of seed (scan order must
// match K4's nodelist construction); -1 if outside
__device__ __forceinline__ int locidx(int ni, int nj, int seed) {
    const int odi[13] = {-2,-1,-1,-1, 0, 0, 0, 0, 0, 1, 1, 1, 2};
    const int odj[13] = { 0,-1, 0, 1,-2,-1, 0, 1, 2,-1, 0, 1, 0};
    int si = seed / GRID, sj = seed % GRID;
    int di = ni - si, dj = nj - sj;
    if (abs(di) + abs(dj) > 2) return -1;
    int m = 0;
    #pragma unroll
    for (int t = 0; t < 13; t++) {
        int ii = si + odi[t], jj = sj + odj[t];
        bool valid = (ii >= 0) && (ii < GRID) && (jj >= 0) && (jj < GRID);
        if (odi[t] == di && odj[t] == dj) return m;   // target always in-bounds
        m += valid ? 1 : 0;
    }
    return -1;
}

// ---------------- K1: features + nearest indices ----------------
__global__ __launch_bounds__(128) void k1_feat(const float* __restrict__ agvs,
                                               const float* __restrict__ nodes) {
    int b = blockIdx.x;
    int tid = threadIdx.x;
    __shared__ float featb[NN * NF];
    __shared__ float sn[NN * 2];
    for (int i = tid; i < NN * NF; i += 128) featb[i] = 0.f;
    for (int i = tid; i < NN * 2;  i += 128) sn[i] = nodes[i];
    __syncthreads();

    const float* arow = agvs + (size_t)b * 160;
    if (tid < 70) {
        int a = tid / 7, k = tid % 7;
        float cx = arow[a * 16 + 2 + 2 * k];
        float cy = arow[a * 16 + 3 + 2 * k];
        float best = 3.402823466e38f;
        int bi = 0;
        for (int n = 0; n < NN; n++) {
            float dx = cx - sn[2 * n];
            float dy = cy - sn[2 * n + 1];
            float d = dx * dx + dy * dy;
            if (d < best) { best = d; bi = n; }
        }
        if (a == 0) {
            atomicAdd(&featb[bi * NF + k], 1.0f);
            if (k == 1) g_seed[b] = bi;
        } else {
            atomicAdd(&featb[bi * NF + 7 + k], 1.0f);
        }
    }
    float c6 = arow[6], c7 = arow[7];
    for (int n = tid; n < NN; n += 128) {
        float dx = sn[2 * n] - c6, dy = sn[2 * n + 1] - c7;
        featb[n * NF + 14] = sqrtf(dx * dx + dy * dy);
    }
    __syncthreads();
    for (int i = tid; i < NN * NF; i += 128) {
        int n = i / NF, k = i % NF;
        g_feat[((size_t)n * BSZ + b) * NF + k] = featb[i];
    }
}

// ---------------- block reduce helper (256 threads) ----------------
__device__ __forceinline__ float blockReduce256(float v, float* red) {
    int tid = threadIdx.x;
    red[tid] = v; __syncthreads();
    #pragma unroll
    for (int o = 128; o > 0; o >>= 1) {
        if (tid < o) red[tid] += red[tid + o];
        __syncthreads();
    }
    float r = red[0];
    __syncthreads();
    return r;
}

// ---------------- K2a: BN1 stats only (no h0 materialization) ----------------
__global__ __launch_bounds__(256) void k2_stats(const float* __restrict__ W0,
                                                const float* __restrict__ b0,
                                                const float* __restrict__ g1,
                                                const float* __restrict__ be1) {
    int n = blockIdx.x;
    int tid = threadIdx.x;                 // channel
    __shared__ float sfeatP[128 * 16];     // padded rows
    __shared__ float red[256];
    float w0r[15];
    #pragma unroll
    for (int f = 0; f < 15; f++) w0r[f] = W0[f * H1 + tid];
    float bias = b0[tid];
    float s = 0.f, s2 = 0.f;
    for (int ch = 0; ch < 4; ch++) {
        __syncthreads();
        const float* src = g_feat + ((size_t)n * BSZ + ch * 128) * NF;
        for (int i = tid; i < 128 * 15; i += 256)
            sfeatP[(i / 15) * 16 + (i % 15)] = src[i];
        __syncthreads();
        for (int r = 0; r < 128; r++) {
            const float4* fp = (const float4*)&sfeatP[r * 16];
            float4 f0 = fp[0], f1 = fp[1], f2 = fp[2], f3 = fp[3];
            float v = bias;
            v = fmaf(f0.x, w0r[0], v);  v = fmaf(f0.y, w0r[1], v);
            v = fmaf(f0.z, w0r[2], v);  v = fmaf(f0.w, w0r[3], v);
            v = fmaf(f1.x, w0r[4], v);  v = fmaf(f1.y, w0r[5], v);
            v = fmaf(f1.z, w0r[6], v);  v = fmaf(f1.w, w0r[7], v);
            v = fmaf(f2.x, w0r[8], v);  v = fmaf(f2.y, w0r[9], v);
            v = fmaf(f2.z, w0r[10], v); v = fmaf(f2.w, w0r[11], v);
            v = fmaf(f3.x, w0r[12], v); v = fmaf(f3.y, w0r[13], v);
            v = fmaf(f3.z, w0r[14], v);
            v = fmaxf(v, 0.f);
            s += v; s2 = fmaf(v, v, s2);
        }
    }
    float tot  = blockReduce256(s, red);
    float tot2 = blockReduce256(s2, red);
    if (tid == 0) {
        const float cnt = (float)(BSZ * H1);
        float m = tot / cnt;
        float var = tot2 / cnt - m * m;
        float a = g1[n] * rsqrtf(var + EPSF);
        g_a1[n] = a;
        g_d1[n] = be1[n] - m * a;
    }
}

// ---------------- K2b: colsum(W1), zero BN2 stats ----------------
__global__ void k2b_prep(const float* __restrict__ W1) {
    int t = threadIdx.x;
    if (t < EDIM) {
        float s = 0.f;
        for (int c = 0; c < H1; c++) s += W1[c * EDIM + t];
        g_S1[t] = s;
    }
    if (t < NN) { g_s2[t] = 0.f; g_ss2[t] = 0.f; }
}

// ---------------- K3: fused h0-recompute + SGEMM (FFMA2) + BN2 stats + compact store ----
#define BM 128
#define KT 16
__global__ __launch_bounds__(256, 2) void k3_fused(const float* __restrict__ W0,
                                                   const float* __restrict__ b0,
                                                   const float* __restrict__ W1,
                                                   const float* __restrict__ b1) {
    const int tid = threadIdx.x;
    const int mtile = blockIdx.x;                 // 0..1599
    const int n = mtile >> 2;
    const int bbase = (mtile & 3) * BM;

    __shared__ __align__(16) float sW0[NF * H1];      // 15 KB
    __shared__ __align__(16) float sb0v[H1];          // 1 KB
    __shared__ __align__(16) float sfeatP[BM * 16];   // 8 KB (padded rows)
    __shared__ __align__(16) float As_s[KT * BM];     // 8 KB
    __shared__ __align__(16) float Bs_s[KT * EDIM];   // 8 KB
    __shared__ float red[256];

    // initial loads
    for (int i = tid; i < NF * H1; i += 256) sW0[i] = W0[i];
    if (tid < H1) sb0v[tid] = b0[tid];
    {
        const float* src = g_feat + ((size_t)n * BSZ + bbase) * NF;
        for (int i = tid; i < BM * 15; i += 256)
            sfeatP[(i / 15) * 16 + (i % 15)] = src[i];
    }

    const int trow = tid >> 4, tcol = tid & 15;
    const int trow8 = trow * 8, tcol8 = tcol * 8;

    // B tile load mapping: 2 float4 per thread
    const int bk0 = tid >> 5;                 // 0..7
    const int bj0 = (tid & 31) << 2;          // 0..124
    float4 pb0 = *reinterpret_cast<const float4*>(W1 + (size_t)bk0 * EDIM + bj0);
    float4 pb1 = *reinterpret_cast<const float4*>(W1 + (size_t)(bk0 + 8) * EDIM + bj0);

    // recompute mapping
    const int rrow = tid & 127;
    const int khalf = tid >> 7;

    unsigned long long accp[8][4];
    #pragma unroll
    for (int i = 0; i < 8; i++)
        #pragma unroll
        for (int j = 0; j < 4; j++) accp[i][j] = 0ULL;

    __syncthreads();   // sW0 / sb0 / sfeat ready

    #pragma unroll 1
    for (int kt = 0; kt < H1 / KT; kt++) {
        // ---- fill: store B tile, compute A tile (h0 recompute) ----
        *reinterpret_cast<float4*>(&Bs_s[bk0 * EDIM + bj0]) = pb0;
        *reinterpret_cast<float4*>(&Bs_s[(bk0 + 8) * EDIM + bj0]) = pb1;
        {
            const int kg = kt * KT + khalf * 8;
            float4 bb0 = *reinterpret_cast<const float4*>(&sb0v[kg]);
            float4 bb1 = *reinterpret_cast<const float4*>(&sb0v[kg + 4]);
            float v[8] = {bb0.x, bb0.y, bb0.z, bb0.w, bb1.x, bb1.y, bb1.z, bb1.w};
            const float* frow = &sfeatP[rrow * 16];
            #pragma unroll
            for (int f = 0; f < 15; f++) {
                float fe = frow[f];
                float4 w0 = *reinterpret_cast<const float4*>(&sW0[f * H1 + kg]);
                float4 w1v = *reinterpret_cast<const float4*>(&sW0[f * H1 + kg + 4]);
                v[0] = fmaf(fe, w0.x, v[0]);  v[1] = fmaf(fe, w0.y, v[1]);
                v[2] = fmaf(fe, w0.z, v[2]);  v[3] = fmaf(fe, w0.w, v[3]);
                v[4] = fmaf(fe, w1v.x, v[4]); v[5] = fmaf(fe, w1v.y, v[5]);
                v[6] = fmaf(fe, w1v.z, v[6]); v[7] = fmaf(fe, w1v.w, v[7]);
            }
            #pragma unroll
            for (int t = 0; t < 8; t++)
                As_s[(khalf * 8 + t) * BM + rrow] = fmaxf(v[t], 0.f);
        }
        __syncthreads();

        // prefetch next B tile
        if (kt + 1 < H1 / KT) {
            int k0 = (kt + 1) * KT;
            pb0 = *reinterpret_cast<const float4*>(W1 + (size_t)(k0 + bk0) * EDIM + bj0);
            pb1 = *reinterpret_cast<const float4*>(W1 + (size_t)(k0 + bk0 + 8) * EDIM + bj0);
        }

        // ---- consume: 16 k-steps of 8x8 outer product via FFMA2 ----
        #pragma unroll
        for (int k = 0; k < KT; k++) {
            float4 a0 = *reinterpret_cast<const float4*>(&As_s[k * BM + trow8]);
            float4 a1 = *reinterpret_cast<const float4*>(&As_s[k * BM + trow8 + 4]);
            ulonglong2 bp0 = *reinterpret_cast<const ulonglong2*>(&Bs_s[k * EDIM + tcol8]);
            ulonglong2 bp1 = *reinterpret_cast<const ulonglong2*>(&Bs_s[k * EDIM + tcol8 + 4]);
            unsigned long long bb[4] = {bp0.x, bp0.y, bp1.x, bp1.y};
            float ar[8] = {a0.x, a0.y, a0.z, a0.w, a1.x, a1.y, a1.z, a1.w};
            #pragma unroll
            for (int i = 0; i < 8; i++) {
                unsigned long long ad = pack2f(ar[i]);
                #pragma unroll
                for (int j = 0; j < 4; j++)
                    accp[i][j] = ffma2(ad, bb[j], accp[i][j]);
            }
        }
        __syncthreads();
    }

    // ---- epilogue: BN1 fold + relu, BN2 stats, compact masked store ----
    const float a1v = g_a1[n], d1v = g_d1[n];
    const int ni = n / GRID, nj = n % GRID;
    float S1r[8], b1r[8];
    #pragma unroll
    for (int j = 0; j < 8; j++) { S1r[j] = g_S1[tcol8 + j]; b1r[j] = b1[tcol8 + j]; }

    float s = 0.f, s2 = 0.f;
    #pragma unroll
    for (int i = 0; i < 8; i++) {
        int b = bbase + trow8 + i;
        float v[8];
        #pragma unroll
        for (int j2 = 0; j2 < 4; j2++) {
            float2 p = unpack2(accp[i][j2]);
            v[2 * j2]     = fmaxf(fmaf(a1v, p.x, fmaf(d1v, S1r[2 * j2],     b1r[2 * j2])),     0.f);
            v[2 * j2 + 1] = fmaxf(fmaf(a1v, p.y, fmaf(d1v, S1r[2 * j2 + 1], b1r[2 * j2 + 1])), 0.f);
        }
        #pragma unroll
        for (int j = 0; j < 8; j++) { s += v[j]; s2 = fmaf(v[j], v[j], s2); }
        int m = locidx(ni, nj, g_seed[b]);
        if (m >= 0) {
            float* dst = g_xc + ((size_t)b * 13 + m) * EDIM + tcol8;
            *reinterpret_cast<float4*>(dst)     = make_float4(v[0], v[1], v[2], v[3]);
            *reinterpret_cast<float4*>(dst + 4) = make_float4(v[4], v[5], v[6], v[7]);
        }
    }
    float tot  = blockReduce256(s, red);
    float tot2 = blockReduce256(s2, red);
    if (tid == 0) {
        atomicAdd(&g_s2[n], tot);
        atomicAdd(&g_ss2[n], tot2);
    }
}

// ---------------- K2c: finalize BN2 affine ----------------
__global__ void k2c_fin(const float* __restrict__ g2, const float* __restrict__ be2) {
    int n = blockIdx.x * blockDim.x + threadIdx.x;
    if (n < NN) {
        const float cnt = (float)(BSZ * EDIM);
        float m = g_s2[n] / cnt;
        float var = g_ss2[n] / cnt - m * m;
        float a = g2[n] * rsqrtf(var + EPSF);
        g_a2[n] = a;
        g_d2[n] = be2[n] - m * a;
    }
}

// ---------------- K4: masked 2-hop graph conv + output ----------------
__global__ __launch_bounds__(128) void k4_conv(const float* __restrict__ Wc,
                                               const float* __restrict__ bc,
                                               float* __restrict__ out) {
    int b = blockIdx.x;
    int tid = threadIdx.x;   // channel
    __shared__ float xs[13][EDIM];
    __shared__ float hs[13][EDIM];
    __shared__ int   nodelist[13];
    __shared__ float dinv_s[13];
    __shared__ int   locmap[25];
    __shared__ int   cnt_s;

    int seed = g_seed[b];
    int si = seed / GRID, sj = seed % GRID;
    if (tid == 0) {
        int cnt = 0;
        for (int di = -2; di <= 2; di++)
            for (int dj = -2; dj <= 2; dj++) {
                int lm = -1;
                if (abs(di) + abs(dj) <= 2) {
                    int i = si + di, j = sj + dj;
                    if (i >= 0 && i < GRID && j >= 0 && j < GRID) {
                        lm = cnt;
                        nodelist[cnt] = i * GRID + j;
                        cnt++;
                    }
                }
                locmap[(di + 2) * 5 + (dj + 2)] = lm;
            }
        cnt_s = cnt;
    }
    __syncthreads();
    const int M = cnt_s;

    if (tid < M) {
        int n = nodelist[tid];
        int i = n / GRID, j = n % GRID;
        int di = i - si + 2, dj = j - sj + 2;
        int nb = 0;
        if (di - 1 >= 0 && locmap[(di - 1) * 5 + dj] >= 0) nb++;
        if (di + 1 < 5  && locmap[(di + 1) * 5 + dj] >= 0) nb++;
        if (dj - 1 >= 0 && locmap[di * 5 + dj - 1] >= 0) nb++;
        if (dj + 1 < 5  && locmap[di * 5 + dj + 1] >= 0) nb++;
        dinv_s[tid] = rsqrtf((float)(1 + nb));
    }
    __syncthreads();

    // load BN2-affined x at masked nodes (compact buffer); zero-pad unused rows
    for (int m = 0; m < 13; m++) {
        if (m < M) {
            int n = nodelist[m];
            xs[m][tid] = fmaf(g_a2[n], g_xc[((size_t)b * 13 + m) * EDIM + tid], g_d2[n]);
        } else {
            xs[m][tid] = 0.f;
        }
    }
    __syncthreads();

    for (int it = 0; it < 2; it++) {
        const float* wc = Wc + (size_t)it * EDIM * EDIM;
        float acc[13];
        #pragma unroll
        for (int m = 0; m < 13; m++) acc[m] = 0.f;
        #pragma unroll 4
        for (int c = 0; c < EDIM; c++) {
            float w = __ldg(wc + (size_t)c * EDIM + tid);
            #pragma unroll
            for (int m = 0; m < 13; m++) acc[m] = fmaf(xs[m][c], w, acc[m]);
        }
        #pragma unroll
        for (int m = 0; m < 13; m++) hs[m][tid] = acc[m];
        __syncthreads();
        float bcv = bc[it * EDIM + tid];
        for (int m = 0; m < M; m++) {
            int n = nodelist[m];
            int i = n / GRID, j = n % GRID;
            int di = i - si + 2, dj = j - sj + 2;
            float dm = dinv_s[m];
            float a = dm * dm * hs[m][tid];
            int u;
            if (di - 1 >= 0 && (u = locmap[(di - 1) * 5 + dj]) >= 0) a = fmaf(dinv_s[u] * dm, hs[u][tid], a);
            if (di + 1 < 5  && (u = locmap[(di + 1) * 5 + dj]) >= 0) a = fmaf(dinv_s[u] * dm, hs[u][tid], a);
            if (dj - 1 >= 0 && (u = locmap[di * 5 + dj - 1]) >= 0) a = fmaf(dinv_s[u] * dm, hs[u][tid], a);
            if (dj + 1 < 5  && (u = locmap[di * 5 + dj + 1]) >= 0) a = fmaf(dinv_s[u] * dm, hs[u][tid], a);
            xs[m][tid] = a + bcv;
        }
        __syncthreads();
    }

    float s = 0.f;
    for (int m = 0; m < M; m++) s += xs[m][tid];
    out[(size_t)b * EDIM + tid] = s / (float)M;
}

// ---------------- launch ----------------
extern "C" void kernel_launch(void* const* d_in, const int* in_sizes, int n_in,
                              void* d_out, int out_size) {
    const float* agvs  = (const float*)d_in[0];
    const float* nodes = (const float*)d_in[1];
    // d_in[2] = edge_index (fixed 4-neighbor grid, handled analytically)
    const float* W0  = (const float*)d_in[3];
    const float* b0  = (const float*)d_in[4];
    const float* g1  = (const float*)d_in[5];
    const float* be1 = (const float*)d_in[6];
    const float* W1  = (const float*)d_in[7];
    const float* b1  = (const float*)d_in[8];
    const float* g2  = (const float*)d_in[9];
    const float* be2 = (const float*)d_in[10];
    const float* Wc  = (const float*)d_in[11];
    const float* bc  = (const float*)d_in[12];
    float* out = (float*)d_out;

    k1_feat <<<BSZ, 128>>>(agvs, nodes);
    k2_stats<<<NN, 256>>>(W0, b0, g1, be1);
    k2b_prep<<<1, 512>>>(W1);
    k3_fused<<<(NN * BSZ) / BM, 256>>>(W0, b0, W1, b1);
    k2c_fin <<<1, 512>>>(g2, be2);
    k4_conv <<<BSZ, 128>>>(Wc, bc, out);
}